// round 4
// baseline (speedup 1.0000x reference)
#include <cuda_runtime.h>
#include <math.h>
#include <float.h>

#define DIN   784
#define DH    512
#define DOUT  10
#define BATCH 256

#define KC    8        // k-chunks (split-K)
#define KCH   98       // DIN / KC
#define NB_H  16       // h-tiles
#define HT    32       // h per tile
#define BT    64       // batch per inner iteration
#define NBT   4        // batch iterations

#define GEMM_BLOCKS 128
#define PREP_BLOCKS 20
#define TOTAL_BLOCKS (GEMM_BLOCKS + PREP_BLOCKS)

// dynamic smem layout (floats):  As[64][98] | B1s[98][36] | B2s[98][36]
#define AS_SZ   (BT * KCH)          // 6272
#define BPAD    36
#define B_SZ    (KCH * BPAD)        // 3528
#define SMEM_FLOATS (AS_SZ + 2 * B_SZ)
#define SMEM_BYTES  (SMEM_FLOATS * 4)   // 53312

// ---------------- device scratch ----------------
__device__ __align__(16) float g_pmu[KC * BATCH * DH];
__device__ __align__(16) float g_pq [KC * BATCH * DH];
__device__ __align__(16) float g_Ws2[DOUT * DH];
__device__ __align__(16) float g_w2t[DOUT * DH];
__device__ float g_spb1[DH];
__device__ float g_spb2[DOUT];
__device__ float g_klpartA[GEMM_BLOCKS];
__device__ float g_klpartB[16];

// ---------------- softplus: fast poly for x < -1, exact fallback ----------------
__device__ __forceinline__ float sp_pair(float x, float& lsp) {
    if (x < -1.0f) {
        float u = __expf(x);
        float P = 1.0f + u * (-0.5f + u * (0.33333334f + u * (-0.25f +
                  u * (0.2f + u * (-0.16666667f + u * 0.14285715f)))));
        float d = P - 1.0f;
        float lp = d * (1.0f + d * (-0.5f + d * (0.33333334f + d * (-0.25f))));
        lsp = x + lp;
        return u * P;
    } else {
        float sp = logf(1.0f + expf(x));
        lsp = logf(sp);
        return sp;
    }
}
__device__ __forceinline__ float sp_only(float x) {
    if (x < -1.0f) {
        float u = __expf(x);
        float P = 1.0f + u * (-0.5f + u * (0.33333334f + u * (-0.25f +
                  u * (0.2f + u * (-0.16666667f + u * 0.14285715f)))));
        return u * P;
    }
    return logf(1.0f + expf(x));
}

// ---------------- K1 MEGA: one wave of 148 blocks ----------------
// blocks 0..127 : persistent dual-GEMM strip (32h x 98k), loop over 256 batches
// blocks 128..147: layer-2 prep (softplus(w_sigma2), w_mu2 transpose, biases, KL)
__global__ __launch_bounds__(256) void k1_mega(const float* __restrict__ x,
                                               const float* __restrict__ w_mu1,
                                               const float* __restrict__ w_sigma1,
                                               const float* __restrict__ b_sigma1,
                                               const float* __restrict__ w_mu2,
                                               const float* __restrict__ w_sigma2,
                                               const float* __restrict__ b_sigma2) {
    extern __shared__ float smem[];
    __shared__ float red[8];
    const int tid = threadIdx.x;
    const int id = blockIdx.x;

    if (id >= GEMM_BLOCKS) {
        // ---- prep role ----
        const int pid = id - GEMM_BLOCKS;
        if (pid < 16) {
            float acc = 0.f;
            for (int i = pid * 256 + tid; i < DOUT * DH; i += 16 * 256) {
                float lsp;
                float sp = sp_pair(w_sigma2[i], lsp);
                g_Ws2[i] = sp;
                acc += sp - lsp;
                float v = w_mu2[i];
                acc += v * v;
                g_w2t[(i % DOUT) * DH + (i / DOUT)] = v;
            }
            #pragma unroll
            for (int s = 16; s; s >>= 1) acc += __shfl_xor_sync(0xffffffffu, acc, s);
            if ((tid & 31) == 0) red[tid >> 5] = acc;
            __syncthreads();
            if (tid == 0) {
                float t = 0.f;
                #pragma unroll
                for (int w = 0; w < 8; w++) t += red[w];
                g_klpartB[pid] = t;
            }
        } else if (pid == 16) {
            g_spb1[tid]       = sp_only(b_sigma1[tid]);
            g_spb1[tid + 256] = sp_only(b_sigma1[tid + 256]);
        } else if (pid == 17) {
            if (tid < DOUT) g_spb2[tid] = sp_only(b_sigma2[tid]);
        }
        return;
    }

    // ---- GEMM role ----
    float* As  = smem;                 // [64][98]  (batch-major, natural)
    float* B1s = smem + AS_SZ;         // [98][36]  (k-major)
    float* B2s = B1s + B_SZ;           // [98][36]

    const int bx = id & 15;            // h tile
    const int kc = id >> 4;            // k chunk
    const int n0 = bx * HT;
    const int ks = kc * KCH;

    float klacc = 0.f;

    // B1: w_mu1[k][h] strip, naturally k-major; fold sum of squares
    for (int i = tid; i < KCH * (HT / 4); i += 256) {    // 98*8 float4
        int r = i >> 3, c = i & 7;
        float4 v = *(const float4*)&w_mu1[(ks + r) * DH + n0 + c * 4];
        *(float4*)&B1s[r * BPAD + c * 4] = v;
        klacc += v.x * v.x + v.y * v.y + v.z * v.z + v.w * v.w;
    }
    // B2: softplus(w_sigma1[h][k]) strip, transposed to k-major; fold KL
    for (int i = tid; i < HT * (KCH / 2); i += 256) {    // 32*49 float2
        int h = i / 49, kp = i % 49;
        float2 v = *(const float2*)&w_sigma1[(n0 + h) * DIN + ks + kp * 2];
        float l0, l1;
        float s0 = sp_pair(v.x, l0);
        float s1 = sp_pair(v.y, l1);
        klacc += (s0 - l0) + (s1 - l1);
        B2s[(kp * 2)     * BPAD + h] = s0;
        B2s[(kp * 2 + 1) * BPAD + h] = s1;
    }
    #pragma unroll
    for (int s = 16; s; s >>= 1) klacc += __shfl_xor_sync(0xffffffffu, klacc, s);
    if ((tid & 31) == 0) red[tid >> 5] = klacc;
    __syncthreads();                   // B tiles ready + red ready
    if (tid == 0) {
        float t = 0.f;
        #pragma unroll
        for (int w = 0; w < 8; w++) t += red[w];
        g_klpartA[id] = t;
    }

    const int tx = tid & 7;            // h quad: 8 x 4 = 32
    const int ty = tid >> 3;           // batch pair: 32 x 2 = 64

    for (int bt = 0; bt < NBT; bt++) {
        const int b0 = bt * BT;
        // A tile: x[b][k] natural layout
        for (int i = tid; i < BT * (KCH / 2); i += 256) {   // 64*49 float2
            int r = i / 49, kp = i % 49;
            *(float2*)&As[r * KCH + kp * 2] =
                *(const float2*)&x[(b0 + r) * DIN + ks + kp * 2];
        }
        __syncthreads();

        float amu[2][4] = {}, aq[2][4] = {};
        const float* a0p = &As[(ty * 2) * KCH];
        const float* a1p = &As[(ty * 2 + 1) * KCH];

        #pragma unroll 7
        for (int kk = 0; kk < KCH; kk++) {
            float a0 = a0p[kk];
            float a1 = a1p[kk];
            float4 b1 = *(const float4*)&B1s[kk * BPAD + tx * 4];
            float4 b2 = *(const float4*)&B2s[kk * BPAD + tx * 4];
            float q0 = a0 * a0, q1 = a1 * a1;
            amu[0][0] += a0 * b1.x; amu[0][1] += a0 * b1.y;
            amu[0][2] += a0 * b1.z; amu[0][3] += a0 * b1.w;
            amu[1][0] += a1 * b1.x; amu[1][1] += a1 * b1.y;
            amu[1][2] += a1 * b1.z; amu[1][3] += a1 * b1.w;
            aq [0][0] += q0 * b2.x; aq [0][1] += q0 * b2.y;
            aq [0][2] += q0 * b2.z; aq [0][3] += q0 * b2.w;
            aq [1][0] += q1 * b2.x; aq [1][1] += q1 * b2.y;
            aq [1][2] += q1 * b2.z; aq [1][3] += q1 * b2.w;
        }

        #pragma unroll
        for (int i = 0; i < 2; i++) {
            int b = b0 + ty * 2 + i;
            float4 m = make_float4(amu[i][0], amu[i][1], amu[i][2], amu[i][3]);
            float4 q = make_float4(aq [i][0], aq [i][1], aq [i][2], aq [i][3]);
            *(float4*)&g_pmu[(kc * BATCH + b) * DH + n0 + tx * 4] = m;
            *(float4*)&g_pq [(kc * BATCH + b) * DH + n0 + tx * 4] = q;
        }
        __syncthreads();               // before overwriting As
    }
}

// ---------------- s2 recompute from partials (cross-batch trace gather) ----------------
__device__ __forceinline__ float s2_at(int m, int h, const float* __restrict__ b_mu1) {
    float mu = b_mu1[h];
    #pragma unroll
    for (int c = 0; c < KC; c++) mu += g_pmu[(c * BATCH + m) * DH + h];
    if (mu <= 0.f) return 0.f;
    float q = g_spb1[h];
    #pragma unroll
    for (int c = 0; c < KC; c++) q += g_pq[(c * BATCH + m) * DH + h];
    return q;
}

// ---------------- K2: combine + layer 2 + softmax + sandwich + KL finalize ----------------
#define TRI_N 55
__global__ __launch_bounds__(64) void k2_layer2(const float* __restrict__ b_mu1,
                                                const float* __restrict__ b_mu2,
                                                float* __restrict__ out) {
    __shared__ float sh[2][240];
    __shared__ float kred[2];
    const int warp = threadIdx.x >> 5, lane = threadIdx.x & 31;
    const int b = blockIdx.x * 2 + warp;
    float* S = sh[warp];

    float mid[TRI_N], amu[DOUT], aq[DOUT];
    #pragma unroll
    for (int e = 0; e < TRI_N; e++) mid[e] = 0.f;
    #pragma unroll
    for (int o = 0; o < DOUT; o++) { amu[o] = 0.f; aq[o] = 0.f; }

    #pragma unroll 4
    for (int t = 0; t < DH / 32; t++) {
        int h = t * 32 + lane;
        int idx = b * DH + h;
        float mu = __ldg(b_mu1 + h);
        #pragma unroll
        for (int c = 0; c < KC; c++) mu += g_pmu[c * (BATCH * DH) + idx];
        bool gate = (mu > 0.f);
        float m = gate ? mu : 0.f;
        float s = 0.f;
        if (gate) {
            s = g_spb1[h];
            #pragma unroll
            for (int c = 0; c < KC; c++) s += g_pq[c * (BATCH * DH) + idx];
        }
        float mm = m * m;
        float w[DOUT], sw[DOUT];
        #pragma unroll
        for (int o = 0; o < DOUT; o++) w[o] = __ldg(&g_w2t[o * DH + h]);
        #pragma unroll
        for (int o = 0; o < DOUT; o++) {
            amu[o] += w[o] * m;
            aq [o] += __ldg(&g_Ws2[o * DH + h]) * mm;
            sw [o]  = s * w[o];
        }
        int e = 0;
        #pragma unroll
        for (int o = 0; o < DOUT; o++)
            #pragma unroll
            for (int p = o; p < DOUT; p++)
                mid[e++] += w[o] * sw[p];
    }

    #pragma unroll
    for (int s = 16; s; s >>= 1) {
        #pragma unroll
        for (int e = 0; e < TRI_N; e++) mid[e] += __shfl_xor_sync(0xffffffffu, mid[e], s);
        #pragma unroll
        for (int o = 0; o < DOUT; o++) {
            amu[o] += __shfl_xor_sync(0xffffffffu, amu[o], s);
            aq [o] += __shfl_xor_sync(0xffffffffu, aq [o], s);
        }
    }

    // assemble sigma3 into shared
    {
        int e = 0;
        #pragma unroll
        for (int o = 0; o < DOUT; o++) {
            #pragma unroll
            for (int p = o; p < DOUT; p++) {
                if (lane == (e & 31)) {
                    float v = mid[e];
                    if (o == p) {
                        // faithful replication of reference's flattened-view trace term
                        int n  = DOUT * b + o;
                        int qn = n >> 8;
                        int mn = n & 255;
                        float trf = g_Ws2[qn * DH + 2 * mn]     * s2_at(mn, mn, b_mu1)
                                  + g_Ws2[qn * DH + 2 * mn + 1] * s2_at(mn, 256 + mn, b_mu1);
                        v += trf + aq[o] + g_spb2[o];
                        S[o * DOUT + o] = v;
                        S[210 + o] = amu[o] + __ldg(b_mu2 + o);
                    } else {
                        S[o * DOUT + p] = v;
                        S[p * DOUT + o] = v;
                    }
                }
                e++;
            }
        }
    }
    __syncwarp();

    // softmax
    {
        float v = (lane < DOUT) ? S[210 + lane] : -FLT_MAX;
        float mx = v;
        #pragma unroll
        for (int s = 16; s; s >>= 1) mx = fmaxf(mx, __shfl_xor_sync(0xffffffffu, mx, s));
        float e = (lane < DOUT) ? expf(v - mx) : 0.f;
        float sm = e;
        #pragma unroll
        for (int s = 16; s; s >>= 1) sm += __shfl_xor_sync(0xffffffffu, sm, s);
        if (lane < DOUT) {
            float p = e / sm;
            S[200 + lane] = p;
            out[b * DOUT + lane] = p;
        }
    }
    __syncwarp();

    // qv[k] = sum_j p[j] sig[j][k]
    if (lane < DOUT) {
        float a = 0.f;
        #pragma unroll
        for (int j = 0; j < DOUT; j++) a += S[200 + j] * S[j * DOUT + lane];
        S[220 + lane] = a;
    }
    __syncwarp();
    for (int e = lane; e < DOUT * DOUT; e += 32) {
        int i = e / DOUT, k = e % DOUT;
        S[100 + e] = S[200 + i] * (S[e] - S[220 + k]);
    }
    __syncwarp();
    if (lane < DOUT) {
        float a = 0.f;
        #pragma unroll
        for (int k = 0; k < DOUT; k++) a += S[100 + lane * DOUT + k] * S[200 + k];
        S[230 + lane] = a;
    }
    __syncwarp();
    for (int e = lane; e < DOUT * DOUT; e += 32) {
        int i = e / DOUT, l = e % DOUT;
        out[BATCH * DOUT + b * DOUT * DOUT + e] = S[200 + l] * (S[100 + e] - S[230 + i]);
    }

    // KL finalize (block 0)
    if (blockIdx.x == 0) {
        float a = 0.f;
        for (int i = threadIdx.x; i < GEMM_BLOCKS; i += 64) a += g_klpartA[i];
        if (threadIdx.x < 16) a += g_klpartB[threadIdx.x];
        #pragma unroll
        for (int s = 16; s; s >>= 1) a += __shfl_xor_sync(0xffffffffu, a, s);
        if (lane == 0) kred[warp] = a;
        __syncthreads();
        if (threadIdx.x == 0)
            out[BATCH * DOUT + BATCH * DOUT * DOUT] =
                0.5f * ((kred[0] + kred[1]) - (float)(DH * DIN + DOUT * DH));
    }
}

// ---------------- launch ----------------
extern "C" void kernel_launch(void* const* d_in, const int* in_sizes, int n_in,
                              void* d_out, int out_size) {
    const float* x        = (const float*)d_in[0];
    const float* w_mu1    = (const float*)d_in[1];
    const float* w_sigma1 = (const float*)d_in[2];
    const float* b_mu1    = (const float*)d_in[3];
    const float* b_sigma1 = (const float*)d_in[4];
    const float* w_mu2    = (const float*)d_in[5];
    const float* w_sigma2 = (const float*)d_in[6];
    const float* b_mu2    = (const float*)d_in[7];
    const float* b_sigma2 = (const float*)d_in[8];
    float* out = (float*)d_out;

    cudaFuncSetAttribute(k1_mega, cudaFuncAttributeMaxDynamicSharedMemorySize, SMEM_BYTES);
    k1_mega<<<TOTAL_BLOCKS, 256, SMEM_BYTES>>>(x, w_mu1, w_sigma1, b_sigma1,
                                               w_mu2, w_sigma2, b_sigma2);
    k2_layer2<<<BATCH / 2, 64>>>(b_mu1, b_mu2, out);
}

// round 5
// speedup vs baseline: 1.0957x; 1.0957x over previous
#include <cuda_runtime.h>
#include <math.h>
#include <float.h>

#define DIN   784
#define DH    512
#define DOUT  10
#define BATCH 256

#define KC    8        // k-chunks (split-K)
#define KCH   98       // DIN / KC
#define HT    32       // h per tile
#define BT    64       // batch per inner iteration
#define NBT   4        // batch iterations

#define GEMM_BLOCKS 128
#define PREP_BLOCKS 20
#define TOTAL_BLOCKS (GEMM_BLOCKS + PREP_BLOCKS)

#define AS_SZ   (BT * KCH)
#define BPAD    36
#define B_SZ    (KCH * BPAD)
#define SMEM_FLOATS (AS_SZ + 2 * B_SZ)
#define SMEM_BYTES  (SMEM_FLOATS * 4)

#define TRI_N 55
#define NACC  75       // 55 mid + 10 amu + 10 aq

// ---------------- device scratch ----------------
__device__ __align__(16) float g_pmu[KC * BATCH * DH];
__device__ __align__(16) float g_pq [KC * BATCH * DH];
__device__ __align__(16) float g_Ws2[DOUT * DH];
__device__ __align__(16) float g_w2t[DOUT * DH];
__device__ float g_spb1[DH];
__device__ float g_spb2[DOUT];
__device__ float g_klpartA[GEMM_BLOCKS];
__device__ float g_klpartB[16];

// ---------------- softplus: fast poly for x < -1, exact fallback ----------------
__device__ __forceinline__ float sp_pair(float x, float& lsp) {
    if (x < -1.0f) {
        float u = __expf(x);
        float P = 1.0f + u * (-0.5f + u * (0.33333334f + u * (-0.25f +
                  u * (0.2f + u * (-0.16666667f + u * 0.14285715f)))));
        float d = P - 1.0f;
        float lp = d * (1.0f + d * (-0.5f + d * (0.33333334f + d * (-0.25f))));
        lsp = x + lp;
        return u * P;
    } else {
        float sp = logf(1.0f + expf(x));
        lsp = logf(sp);
        return sp;
    }
}
__device__ __forceinline__ float sp_only(float x) {
    if (x < -1.0f) {
        float u = __expf(x);
        float P = 1.0f + u * (-0.5f + u * (0.33333334f + u * (-0.25f +
                  u * (0.2f + u * (-0.16666667f + u * 0.14285715f)))));
        return u * P;
    }
    return logf(1.0f + expf(x));
}

// ---------------- K1 MEGA: one wave of 148 blocks ----------------
__global__ __launch_bounds__(256) void k1_mega(const float* __restrict__ x,
                                               const float* __restrict__ w_mu1,
                                               const float* __restrict__ w_sigma1,
                                               const float* __restrict__ b_sigma1,
                                               const float* __restrict__ w_mu2,
                                               const float* __restrict__ w_sigma2,
                                               const float* __restrict__ b_sigma2) {
    extern __shared__ float smem[];
    __shared__ float red[8];
    const int tid = threadIdx.x;
    const int id = blockIdx.x;

    if (id >= GEMM_BLOCKS) {
        const int pid = id - GEMM_BLOCKS;
        if (pid < 16) {
            float acc = 0.f;
            for (int i = pid * 256 + tid; i < DOUT * DH; i += 16 * 256) {
                float lsp;
                float sp = sp_pair(w_sigma2[i], lsp);
                g_Ws2[i] = sp;
                acc += sp - lsp;
                float v = w_mu2[i];
                acc += v * v;
                g_w2t[(i % DOUT) * DH + (i / DOUT)] = v;
            }
            #pragma unroll
            for (int s = 16; s; s >>= 1) acc += __shfl_xor_sync(0xffffffffu, acc, s);
            if ((tid & 31) == 0) red[tid >> 5] = acc;
            __syncthreads();
            if (tid == 0) {
                float t = 0.f;
                #pragma unroll
                for (int w = 0; w < 8; w++) t += red[w];
                g_klpartB[pid] = t;
            }
        } else if (pid == 16) {
            g_spb1[tid]       = sp_only(b_sigma1[tid]);
            g_spb1[tid + 256] = sp_only(b_sigma1[tid + 256]);
        } else if (pid == 17) {
            if (tid < DOUT) g_spb2[tid] = sp_only(b_sigma2[tid]);
        }
        return;
    }

    float* As  = smem;
    float* B1s = smem + AS_SZ;
    float* B2s = B1s + B_SZ;

    const int bx = id & 15;
    const int kc = id >> 4;
    const int n0 = bx * HT;
    const int ks = kc * KCH;

    float klacc = 0.f;

    for (int i = tid; i < KCH * (HT / 4); i += 256) {
        int r = i >> 3, c = i & 7;
        float4 v = *(const float4*)&w_mu1[(ks + r) * DH + n0 + c * 4];
        *(float4*)&B1s[r * BPAD + c * 4] = v;
        klacc += v.x * v.x + v.y * v.y + v.z * v.z + v.w * v.w;
    }
    for (int i = tid; i < HT * (KCH / 2); i += 256) {
        int h = i / 49, kp = i % 49;
        float2 v = *(const float2*)&w_sigma1[(n0 + h) * DIN + ks + kp * 2];
        float l0, l1;
        float s0 = sp_pair(v.x, l0);
        float s1 = sp_pair(v.y, l1);
        klacc += (s0 - l0) + (s1 - l1);
        B2s[(kp * 2)     * BPAD + h] = s0;
        B2s[(kp * 2 + 1) * BPAD + h] = s1;
    }
    #pragma unroll
    for (int s = 16; s; s >>= 1) klacc += __shfl_xor_sync(0xffffffffu, klacc, s);
    if ((tid & 31) == 0) red[tid >> 5] = klacc;
    __syncthreads();
    if (tid == 0) {
        float t = 0.f;
        #pragma unroll
        for (int w = 0; w < 8; w++) t += red[w];
        g_klpartA[id] = t;
    }

    const int tx = tid & 7;
    const int ty = tid >> 3;

    for (int bt = 0; bt < NBT; bt++) {
        const int b0 = bt * BT;
        for (int i = tid; i < BT * (KCH / 2); i += 256) {
            int r = i / 49, kp = i % 49;
            *(float2*)&As[r * KCH + kp * 2] =
                *(const float2*)&x[(b0 + r) * DIN + ks + kp * 2];
        }
        __syncthreads();

        float amu[2][4] = {}, aq[2][4] = {};
        const float* a0p = &As[(ty * 2) * KCH];
        const float* a1p = &As[(ty * 2 + 1) * KCH];

        #pragma unroll 7
        for (int kk = 0; kk < KCH; kk++) {
            float a0 = a0p[kk];
            float a1 = a1p[kk];
            float4 b1 = *(const float4*)&B1s[kk * BPAD + tx * 4];
            float4 b2 = *(const float4*)&B2s[kk * BPAD + tx * 4];
            float q0 = a0 * a0, q1 = a1 * a1;
            amu[0][0] += a0 * b1.x; amu[0][1] += a0 * b1.y;
            amu[0][2] += a0 * b1.z; amu[0][3] += a0 * b1.w;
            amu[1][0] += a1 * b1.x; amu[1][1] += a1 * b1.y;
            amu[1][2] += a1 * b1.z; amu[1][3] += a1 * b1.w;
            aq [0][0] += q0 * b2.x; aq [0][1] += q0 * b2.y;
            aq [0][2] += q0 * b2.z; aq [0][3] += q0 * b2.w;
            aq [1][0] += q1 * b2.x; aq [1][1] += q1 * b2.y;
            aq [1][2] += q1 * b2.z; aq [1][3] += q1 * b2.w;
        }

        #pragma unroll
        for (int i = 0; i < 2; i++) {
            int b = b0 + ty * 2 + i;
            float4 m = make_float4(amu[i][0], amu[i][1], amu[i][2], amu[i][3]);
            float4 q = make_float4(aq [i][0], aq [i][1], aq [i][2], aq [i][3]);
            *(float4*)&g_pmu[(kc * BATCH + b) * DH + n0 + tx * 4] = m;
            *(float4*)&g_pq [(kc * BATCH + b) * DH + n0 + tx * 4] = q;
        }
        __syncthreads();
    }
}

// ---------------- s2 recompute from partials (cross-batch trace gather) ----------------
__device__ __forceinline__ float s2_at(int m, int h, const float* __restrict__ b_mu1) {
    float mu = b_mu1[h];
    #pragma unroll
    for (int c = 0; c < KC; c++) mu += g_pmu[(c * BATCH + m) * DH + h];
    if (mu <= 0.f) return 0.f;
    float q = g_spb1[h];
    #pragma unroll
    for (int c = 0; c < KC; c++) q += g_pq[(c * BATCH + m) * DH + h];
    return q;
}

// ---------------- K2: one block per batch, 128 threads ----------------
__global__ __launch_bounds__(128) void k2_layer2(const float* __restrict__ b_mu1,
                                                 const float* __restrict__ b_mu2,
                                                 float* __restrict__ out) {
    __shared__ float m2s[DH], s2s[DH];
    __shared__ float wp[4][NACC + 1];           // per-warp partials
    __shared__ float S[240];                    // sig[0..99] t1[100..199] p[200..209]
                                                // mus[210..219] qv[220] rr[230]
    __shared__ float saq[DOUT];
    __shared__ float kred[4];

    const int tid = threadIdx.x;
    const int warp = tid >> 5, lane = tid & 31;
    const int b = blockIdx.x;
    const int SZ = BATCH * DH;

    // ---- phase 1: combine split-K partials + bias + ReLU into smem ----
    #pragma unroll
    for (int j = 0; j < 4; j++) {
        int h = j * 128 + tid;
        int idx = b * DH + h;
        float mu = __ldg(b_mu1 + h);
        #pragma unroll
        for (int c = 0; c < KC; c++) mu += g_pmu[c * SZ + idx];
        bool gate = (mu > 0.f);
        float s = 0.f;
        if (gate) {
            s = g_spb1[h];
            #pragma unroll
            for (int c = 0; c < KC; c++) s += g_pq[c * SZ + idx];
        }
        m2s[h] = gate ? mu : 0.f;
        s2s[h] = s;
    }
    __syncthreads();

    // ---- phase 2: each warp covers 128 h, 75 accumulators ----
    float mid[TRI_N], amu[DOUT], aq[DOUT];
    #pragma unroll
    for (int e = 0; e < TRI_N; e++) mid[e] = 0.f;
    #pragma unroll
    for (int o = 0; o < DOUT; o++) { amu[o] = 0.f; aq[o] = 0.f; }

    #pragma unroll
    for (int t = 0; t < 4; t++) {
        int h = warp * 128 + t * 32 + lane;
        float m = m2s[h];
        float s = s2s[h];
        float mm = m * m;
        float w[DOUT], sw[DOUT];
        #pragma unroll
        for (int o = 0; o < DOUT; o++) w[o] = __ldg(&g_w2t[o * DH + h]);
        #pragma unroll
        for (int o = 0; o < DOUT; o++) {
            amu[o] += w[o] * m;
            aq [o] += __ldg(&g_Ws2[o * DH + h]) * mm;
            sw [o]  = s * w[o];
        }
        int e = 0;
        #pragma unroll
        for (int o = 0; o < DOUT; o++)
            #pragma unroll
            for (int p = o; p < DOUT; p++)
                mid[e++] += w[o] * sw[p];
    }

    #pragma unroll
    for (int s = 16; s; s >>= 1) {
        #pragma unroll
        for (int e = 0; e < TRI_N; e++) mid[e] += __shfl_xor_sync(0xffffffffu, mid[e], s);
        #pragma unroll
        for (int o = 0; o < DOUT; o++) {
            amu[o] += __shfl_xor_sync(0xffffffffu, amu[o], s);
            aq [o] += __shfl_xor_sync(0xffffffffu, aq [o], s);
        }
    }
    // lanes cooperatively store warp partials (acc order: mid, amu, aq)
    #pragma unroll
    for (int r = 0; r < 3; r++) {
        int e = r * 32 + lane;
        if (e < NACC) {
            float v;
            if (e < TRI_N)      v = mid[e];
            else if (e < 65)    v = amu[e - TRI_N];
            else                v = aq [e - 65];
            wp[warp][e] = v;
        }
    }
    __syncthreads();

    // ---- assembly: threads 0..74 ----
    if (tid < NACC) {
        float v = wp[0][tid] + wp[1][tid] + wp[2][tid] + wp[3][tid];
        if (tid < TRI_N) {
            int o = 0, rem = tid;
            #pragma unroll
            for (int r = 0; r < DOUT; r++) {
                if (rem >= DOUT - r && o == r) { rem -= DOUT - r; o = r + 1; }
            }
            int p = o + rem;
            S[o * DOUT + p] = v;
            S[p * DOUT + o] = v;
        } else if (tid < 65) {
            int o = tid - TRI_N;
            S[210 + o] = v + __ldg(b_mu2 + o);
        } else {
            saq[tid - 65] = v;
        }
    }
    __syncthreads();
    if (tid < DOUT) {
        // faithful replication of reference's flattened-view trace term
        int n  = DOUT * b + tid;
        int qn = n >> 8;
        int mn = n & 255;
        float trf = g_Ws2[qn * DH + 2 * mn]     * s2_at(mn, mn, b_mu1)
                  + g_Ws2[qn * DH + 2 * mn + 1] * s2_at(mn, 256 + mn, b_mu1);
        S[tid * DOUT + tid] += trf + saq[tid] + g_spb2[tid];
    }
    __syncthreads();

    // ---- softmax + sandwich (warp 0) ----
    if (warp == 0) {
        float v = (lane < DOUT) ? S[210 + lane] : -FLT_MAX;
        float mx = v;
        #pragma unroll
        for (int s = 16; s; s >>= 1) mx = fmaxf(mx, __shfl_xor_sync(0xffffffffu, mx, s));
        float e = (lane < DOUT) ? expf(v - mx) : 0.f;
        float sm = e;
        #pragma unroll
        for (int s = 16; s; s >>= 1) sm += __shfl_xor_sync(0xffffffffu, sm, s);
        if (lane < DOUT) {
            float p = e / sm;
            S[200 + lane] = p;
            out[b * DOUT + lane] = p;
        }
        __syncwarp();

        if (lane < DOUT) {
            float a = 0.f;
            #pragma unroll
            for (int j = 0; j < DOUT; j++) a += S[200 + j] * S[j * DOUT + lane];
            S[220 + lane] = a;
        }
        __syncwarp();
        for (int e2 = lane; e2 < DOUT * DOUT; e2 += 32) {
            int i = e2 / DOUT, k = e2 % DOUT;
            S[100 + e2] = S[200 + i] * (S[e2] - S[220 + k]);
        }
        __syncwarp();
        if (lane < DOUT) {
            float a = 0.f;
            #pragma unroll
            for (int k = 0; k < DOUT; k++) a += S[100 + lane * DOUT + k] * S[200 + k];
            S[230 + lane] = a;
        }
        __syncwarp();
        for (int e2 = lane; e2 < DOUT * DOUT; e2 += 32) {
            int i = e2 / DOUT, l = e2 % DOUT;
            out[BATCH * DOUT + b * DOUT * DOUT + e2] = S[200 + l] * (S[100 + e2] - S[230 + i]);
        }
    }

    // ---- KL finalize (block 0, warp 1..3 free; use whole block) ----
    if (blockIdx.x == 0) {
        float a = 0.f;
        for (int i = tid; i < GEMM_BLOCKS; i += 128) a += g_klpartA[i];
        if (tid < 16) a += g_klpartB[tid];
        #pragma unroll
        for (int s = 16; s; s >>= 1) a += __shfl_xor_sync(0xffffffffu, a, s);
        if (lane == 0) kred[warp] = a;
        __syncthreads();
        if (tid == 0)
            out[BATCH * DOUT + BATCH * DOUT * DOUT] =
                0.5f * ((kred[0] + kred[1] + kred[2] + kred[3])
                        - (float)(DH * DIN + DOUT * DH));
    }
}

// ---------------- launch ----------------
extern "C" void kernel_launch(void* const* d_in, const int* in_sizes, int n_in,
                              void* d_out, int out_size) {
    const float* x        = (const float*)d_in[0];
    const float* w_mu1    = (const float*)d_in[1];
    const float* w_sigma1 = (const float*)d_in[2];
    const float* b_mu1    = (const float*)d_in[3];
    const float* b_sigma1 = (const float*)d_in[4];
    const float* w_mu2    = (const float*)d_in[5];
    const float* w_sigma2 = (const float*)d_in[6];
    const float* b_mu2    = (const float*)d_in[7];
    const float* b_sigma2 = (const float*)d_in[8];
    float* out = (float*)d_out;

    cudaFuncSetAttribute(k1_mega, cudaFuncAttributeMaxDynamicSharedMemorySize, SMEM_BYTES);
    k1_mega<<<TOTAL_BLOCKS, 256, SMEM_BYTES>>>(x, w_mu1, w_sigma1, b_sigma1,
                                               w_mu2, w_sigma2, b_sigma2);
    k2_layer2<<<BATCH, 128>>>(b_mu1, b_mu2, out);
}

// round 6
// speedup vs baseline: 1.2385x; 1.1304x over previous
#include <cuda_runtime.h>
#include <math.h>
#include <float.h>

#define DIN   784
#define DH    512
#define DOUT  10
#define BATCH 256

#define KC    8        // k-chunks (split-K)
#define KCH   98       // DIN / KC
#define HT    32       // h per tile
#define BT    64       // batch per inner iteration
#define NBT   4        // batch iterations

#define GEMM_BLOCKS 128
#define PREP_BLOCKS 20
#define TOTAL_BLOCKS (GEMM_BLOCKS + PREP_BLOCKS)

#define AS_SZ   (BT * KCH)
#define BPAD    36
#define B_SZ    (KCH * BPAD)
#define SMEM_FLOATS (AS_SZ + 2 * B_SZ)
#define SMEM_BYTES  (SMEM_FLOATS * 4)

#define TRI_N 55
#define NACC  75       // 55 mid + 10 amu + 10 aq

// ---------------- device scratch ----------------
__device__ __align__(16) float g_pmu[KC * BATCH * DH];
__device__ __align__(16) float g_pq [KC * BATCH * DH];
__device__ __align__(16) float g_Ws2[DOUT * DH];
__device__ __align__(16) float g_w2t[DOUT * DH];
__device__ float g_spb1[DH];
__device__ float g_spb2[DOUT];
__device__ float g_klpartA[GEMM_BLOCKS];
__device__ float g_klpartB[16];

// ---------------- softplus: fast poly for x < -1, exact fallback ----------------
__device__ __forceinline__ float sp_pair(float x, float& lsp) {
    if (x < -1.0f) {
        float u = __expf(x);
        float P = 1.0f + u * (-0.5f + u * (0.33333334f + u * (-0.25f +
                  u * (0.2f + u * (-0.16666667f + u * 0.14285715f)))));
        float d = P - 1.0f;
        float lp = d * (1.0f + d * (-0.5f + d * (0.33333334f + d * (-0.25f))));
        lsp = x + lp;
        return u * P;
    } else {
        float sp = logf(1.0f + expf(x));
        lsp = logf(sp);
        return sp;
    }
}
__device__ __forceinline__ float sp_only(float x) {
    if (x < -1.0f) {
        float u = __expf(x);
        float P = 1.0f + u * (-0.5f + u * (0.33333334f + u * (-0.25f +
                  u * (0.2f + u * (-0.16666667f + u * 0.14285715f)))));
        return u * P;
    }
    return logf(1.0f + expf(x));
}

// ---------------- K1 MEGA: one wave of 148 blocks ----------------
__global__ __launch_bounds__(256) void k1_mega(const float* __restrict__ x,
                                               const float* __restrict__ w_mu1,
                                               const float* __restrict__ w_sigma1,
                                               const float* __restrict__ b_sigma1,
                                               const float* __restrict__ w_mu2,
                                               const float* __restrict__ w_sigma2,
                                               const float* __restrict__ b_sigma2) {
    extern __shared__ float smem[];
    __shared__ float red[8];
    const int tid = threadIdx.x;
    const int id = blockIdx.x;

    if (id >= GEMM_BLOCKS) {
        const int pid = id - GEMM_BLOCKS;
        if (pid < 16) {
            float acc = 0.f;
            for (int i = pid * 256 + tid; i < DOUT * DH; i += 16 * 256) {
                float lsp;
                float sp = sp_pair(w_sigma2[i], lsp);
                g_Ws2[i] = sp;
                acc += sp - lsp;
                float v = w_mu2[i];
                acc += v * v;
                g_w2t[(i % DOUT) * DH + (i / DOUT)] = v;
            }
            #pragma unroll
            for (int s = 16; s; s >>= 1) acc += __shfl_xor_sync(0xffffffffu, acc, s);
            if ((tid & 31) == 0) red[tid >> 5] = acc;
            __syncthreads();
            if (tid == 0) {
                float t = 0.f;
                #pragma unroll
                for (int w = 0; w < 8; w++) t += red[w];
                g_klpartB[pid] = t;
            }
        } else if (pid == 16) {
            g_spb1[tid]       = sp_only(b_sigma1[tid]);
            g_spb1[tid + 256] = sp_only(b_sigma1[tid + 256]);
        } else if (pid == 17) {
            if (tid < DOUT) g_spb2[tid] = sp_only(b_sigma2[tid]);
        }
        return;
    }

    float* As  = smem;
    float* B1s = smem + AS_SZ;
    float* B2s = B1s + B_SZ;

    const int bx = id & 15;
    const int kc = id >> 4;
    const int n0 = bx * HT;
    const int ks = kc * KCH;

    float klacc = 0.f;

    for (int i = tid; i < KCH * (HT / 4); i += 256) {
        int r = i >> 3, c = i & 7;
        float4 v = *(const float4*)&w_mu1[(ks + r) * DH + n0 + c * 4];
        *(float4*)&B1s[r * BPAD + c * 4] = v;
        klacc += v.x * v.x + v.y * v.y + v.z * v.z + v.w * v.w;
    }
    for (int i = tid; i < HT * (KCH / 2); i += 256) {
        int h = i / 49, kp = i % 49;
        float2 v = *(const float2*)&w_sigma1[(n0 + h) * DIN + ks + kp * 2];
        float l0, l1;
        float s0 = sp_pair(v.x, l0);
        float s1 = sp_pair(v.y, l1);
        klacc += (s0 - l0) + (s1 - l1);
        B2s[(kp * 2)     * BPAD + h] = s0;
        B2s[(kp * 2 + 1) * BPAD + h] = s1;
    }
    #pragma unroll
    for (int s = 16; s; s >>= 1) klacc += __shfl_xor_sync(0xffffffffu, klacc, s);
    if ((tid & 31) == 0) red[tid >> 5] = klacc;
    __syncthreads();
    if (tid == 0) {
        float t = 0.f;
        #pragma unroll
        for (int w = 0; w < 8; w++) t += red[w];
        g_klpartA[id] = t;
    }

    const int tx = tid & 7;
    const int ty = tid >> 3;

    for (int bt = 0; bt < NBT; bt++) {
        const int b0 = bt * BT;
        for (int i = tid; i < BT * (KCH / 2); i += 256) {
            int r = i / 49, kp = i % 49;
            *(float2*)&As[r * KCH + kp * 2] =
                *(const float2*)&x[(b0 + r) * DIN + ks + kp * 2];
        }
        __syncthreads();

        float amu[2][4] = {}, aq[2][4] = {};
        const float* a0p = &As[(ty * 2) * KCH];
        const float* a1p = &As[(ty * 2 + 1) * KCH];

        #pragma unroll 7
        for (int kk = 0; kk < KCH; kk++) {
            float a0 = a0p[kk];
            float a1 = a1p[kk];
            float4 b1 = *(const float4*)&B1s[kk * BPAD + tx * 4];
            float4 b2 = *(const float4*)&B2s[kk * BPAD + tx * 4];
            float q0 = a0 * a0, q1 = a1 * a1;
            amu[0][0] += a0 * b1.x; amu[0][1] += a0 * b1.y;
            amu[0][2] += a0 * b1.z; amu[0][3] += a0 * b1.w;
            amu[1][0] += a1 * b1.x; amu[1][1] += a1 * b1.y;
            amu[1][2] += a1 * b1.z; amu[1][3] += a1 * b1.w;
            aq [0][0] += q0 * b2.x; aq [0][1] += q0 * b2.y;
            aq [0][2] += q0 * b2.z; aq [0][3] += q0 * b2.w;
            aq [1][0] += q1 * b2.x; aq [1][1] += q1 * b2.y;
            aq [1][2] += q1 * b2.z; aq [1][3] += q1 * b2.w;
        }

        #pragma unroll
        for (int i = 0; i < 2; i++) {
            int b = b0 + ty * 2 + i;
            float4 m = make_float4(amu[i][0], amu[i][1], amu[i][2], amu[i][3]);
            float4 q = make_float4(aq [i][0], aq [i][1], aq [i][2], aq [i][3]);
            *(float4*)&g_pmu[(kc * BATCH + b) * DH + n0 + tx * 4] = m;
            *(float4*)&g_pq [(kc * BATCH + b) * DH + n0 + tx * 4] = q;
        }
        __syncthreads();
    }
}

// ---------------- s2 recompute from partials (cross-batch trace gather) ----------------
__device__ __forceinline__ float s2_at(int m, int h, const float* __restrict__ b_mu1) {
    float mu = b_mu1[h];
    #pragma unroll
    for (int c = 0; c < KC; c++) mu += g_pmu[(c * BATCH + m) * DH + h];
    if (mu <= 0.f) return 0.f;
    float q = g_spb1[h];
    #pragma unroll
    for (int c = 0; c < KC; c++) q += g_pq[(c * BATCH + m) * DH + h];
    return q;
}

// ---------------- per-warp accumulator strip: owns acc indices [LO, HI), sweeps all h ----------------
// acc index space: 0..54 = mid (upper-tri o<=p), 55..64 = amu[o], 65..74 = aq[o]
template<int LO, int HI>
__device__ __forceinline__ void accum_strip(const float* __restrict__ m2s,
                                            const float* __restrict__ s2s,
                                            const float* __restrict__ w2s,
                                            float* __restrict__ wp,
                                            int lane) {
    float acc[HI - LO];
    #pragma unroll
    for (int j = 0; j < HI - LO; j++) acc[j] = 0.f;

    #pragma unroll 4
    for (int t = 0; t < DH / 32; t++) {
        int h = t * 32 + lane;
        float m = m2s[h];
        float s = s2s[h];
        float mm = m * m;
        float w[DOUT], sw[DOUT];
        #pragma unroll
        for (int o = 0; o < DOUT; o++) w[o] = w2s[o * DH + h];
        #pragma unroll
        for (int o = 0; o < DOUT; o++) sw[o] = s * w[o];   // DCE'd if no mid owned
        {
            int e = 0;
            #pragma unroll
            for (int o = 0; o < DOUT; o++)
                #pragma unroll
                for (int p = o; p < DOUT; p++) {
                    if (e >= LO && e < HI) acc[e - LO] += w[p] * sw[o];
                    e++;
                }
        }
        #pragma unroll
        for (int o = 0; o < DOUT; o++)
            if (TRI_N + o >= LO && TRI_N + o < HI) acc[TRI_N + o - LO] += w[o] * m;
        #pragma unroll
        for (int o = 0; o < DOUT; o++)
            if (65 + o >= LO && 65 + o < HI) acc[65 + o - LO] += __ldg(&g_Ws2[o * DH + h]) * mm;
    }

    #pragma unroll
    for (int s = 16; s; s >>= 1)
        #pragma unroll
        for (int j = 0; j < HI - LO; j++)
            acc[j] += __shfl_xor_sync(0xffffffffu, acc[j], s);

    #pragma unroll
    for (int j = 0; j < HI - LO; j++)
        if (lane == j) wp[LO + j] = acc[j];
}

// ---------------- K2: one block per batch, 128 threads, warp-partitioned accumulators ----------------
__global__ __launch_bounds__(128) void k2_layer2(const float* __restrict__ b_mu1,
                                                 const float* __restrict__ b_mu2,
                                                 float* __restrict__ out) {
    __shared__ float m2s[DH], s2s[DH];
    __shared__ float w2s[DOUT * DH];            // 20KB
    __shared__ float wp[NACC];
    __shared__ float S[240];                    // sig[0..99] t1[100..199] p[200..209]
                                                // mus[210..219] qv[220..229] rr[230..239]
    __shared__ float saq[DOUT];
    __shared__ float kred[4];

    const int tid = threadIdx.x;
    const int warp = tid >> 5, lane = tid & 31;
    const int b = blockIdx.x;
    const int SZ = BATCH * DH;

    // ---- phase 1: combine split-K partials + bias + ReLU; stage w2t in smem ----
    #pragma unroll
    for (int j = 0; j < 4; j++) {
        int h = j * 128 + tid;
        int idx = b * DH + h;
        float mu = __ldg(b_mu1 + h);
        #pragma unroll
        for (int c = 0; c < KC; c++) mu += g_pmu[c * SZ + idx];
        bool gate = (mu > 0.f);
        float s = 0.f;
        if (gate) {
            s = g_spb1[h];
            #pragma unroll
            for (int c = 0; c < KC; c++) s += g_pq[c * SZ + idx];
        }
        m2s[h] = gate ? mu : 0.f;
        s2s[h] = s;
    }
    for (int i = tid; i < DOUT * DH; i += 128) w2s[i] = g_w2t[i];
    __syncthreads();

    // ---- phase 2: each warp owns a strip of the 75 accumulators, sweeps all 512 h ----
    if      (warp == 0) accum_strip< 0, 19>(m2s, s2s, w2s, wp, lane);
    else if (warp == 1) accum_strip<19, 38>(m2s, s2s, w2s, wp, lane);
    else if (warp == 2) accum_strip<38, 57>(m2s, s2s, w2s, wp, lane);
    else                accum_strip<57, 75>(m2s, s2s, w2s, wp, lane);
    __syncthreads();

    // ---- assembly: threads 0..74 scatter into sigma3 / mus / aq ----
    if (tid < NACC) {
        float v = wp[tid];
        if (tid < TRI_N) {
            int o = 0, rem = tid;
            #pragma unroll
            for (int r = 0; r < DOUT; r++) {
                if (rem >= DOUT - r && o == r) { rem -= DOUT - r; o = r + 1; }
            }
            int p = o + rem;
            S[o * DOUT + p] = v;
            S[p * DOUT + o] = v;
        } else if (tid < 65) {
            int o = tid - TRI_N;
            S[210 + o] = v + __ldg(b_mu2 + o);
        } else {
            saq[tid - 65] = v;
        }
    }
    __syncthreads();
    if (tid < DOUT) {
        // faithful replication of reference's flattened-view trace term
        int n  = DOUT * b + tid;
        int qn = n >> 8;
        int mn = n & 255;
        float trf = g_Ws2[qn * DH + 2 * mn]     * s2_at(mn, mn, b_mu1)
                  + g_Ws2[qn * DH + 2 * mn + 1] * s2_at(mn, 256 + mn, b_mu1);
        S[tid * DOUT + tid] += trf + saq[tid] + g_spb2[tid];
    }
    __syncthreads();

    // ---- softmax + sandwich (warp 0) ----
    if (warp == 0) {
        float v = (lane < DOUT) ? S[210 + lane] : -FLT_MAX;
        float mx = v;
        #pragma unroll
        for (int s = 16; s; s >>= 1) mx = fmaxf(mx, __shfl_xor_sync(0xffffffffu, mx, s));
        float e = (lane < DOUT) ? expf(v - mx) : 0.f;
        float sm = e;
        #pragma unroll
        for (int s = 16; s; s >>= 1) sm += __shfl_xor_sync(0xffffffffu, sm, s);
        if (lane < DOUT) {
            float p = e / sm;
            S[200 + lane] = p;
            out[b * DOUT + lane] = p;
        }
        __syncwarp();

        if (lane < DOUT) {
            float a = 0.f;
            #pragma unroll
            for (int j = 0; j < DOUT; j++) a += S[200 + j] * S[j * DOUT + lane];
            S[220 + lane] = a;
        }
        __syncwarp();
        for (int e2 = lane; e2 < DOUT * DOUT; e2 += 32) {
            int i = e2 / DOUT, k = e2 % DOUT;
            S[100 + e2] = S[200 + i] * (S[e2] - S[220 + k]);
        }
        __syncwarp();
        if (lane < DOUT) {
            float a = 0.f;
            #pragma unroll
            for (int k = 0; k < DOUT; k++) a += S[100 + lane * DOUT + k] * S[200 + k];
            S[230 + lane] = a;
        }
        __syncwarp();
        for (int e2 = lane; e2 < DOUT * DOUT; e2 += 32) {
            int i = e2 / DOUT, l = e2 % DOUT;
            out[BATCH * DOUT + b * DOUT * DOUT + e2] = S[200 + l] * (S[100 + e2] - S[230 + i]);
        }
    }

    // ---- KL finalize (block 0) ----
    if (blockIdx.x == 0) {
        float a = 0.f;
        for (int i = tid; i < GEMM_BLOCKS; i += 128) a += g_klpartA[i];
        if (tid < 16) a += g_klpartB[tid];
        #pragma unroll
        for (int s = 16; s; s >>= 1) a += __shfl_xor_sync(0xffffffffu, a, s);
        if (lane == 0) kred[warp] = a;
        __syncthreads();
        if (tid == 0)
            out[BATCH * DOUT + BATCH * DOUT * DOUT] =
                0.5f * ((kred[0] + kred[1] + kred[2] + kred[3])
                        - (float)(DH * DIN + DOUT * DH));
    }
}

// ---------------- launch ----------------
extern "C" void kernel_launch(void* const* d_in, const int* in_sizes, int n_in,
                              void* d_out, int out_size) {
    const float* x        = (const float*)d_in[0];
    const float* w_mu1    = (const float*)d_in[1];
    const float* w_sigma1 = (const float*)d_in[2];
    const float* b_mu1    = (const float*)d_in[3];
    const float* b_sigma1 = (const float*)d_in[4];
    const float* w_mu2    = (const float*)d_in[5];
    const float* w_sigma2 = (const float*)d_in[6];
    const float* b_mu2    = (const float*)d_in[7];
    const float* b_sigma2 = (const float*)d_in[8];
    float* out = (float*)d_out;

    cudaFuncSetAttribute(k1_mega, cudaFuncAttributeMaxDynamicSharedMemorySize, SMEM_BYTES);
    k1_mega<<<TOTAL_BLOCKS, 256, SMEM_BYTES>>>(x, w_mu1, w_sigma1, b_sigma1,
                                               w_mu2, w_sigma2, b_sigma2);
    k2_layer2<<<BATCH, 128>>>(b_mu1, b_mu2, out);
}